// round 10
// baseline (speedup 1.0000x reference)
#include <cuda_runtime.h>
#include <cuda_fp16.h>
#include <cstdint>

// ============================ problem sizes ============================
#define BB    32
#define CIN   256
#define COUT  512
#define HWSZ  4096                  // 64*64
#define KTOT  256
#define NPIX  131072.0f             // B*H*W per channel

// ============================ device scratch ============================
__device__ __align__(128) float  g_noise[CIN * HWSZ];   // 4 MB
__device__ __align__(128) __half g_w[COUT * KTOT];      // 256 KB [o][c]
__device__ __align__(128) float  g_C[CIN * CIN];        // 256 KB  A^T A
__device__ float  g_S[CIN];                             // column sums of A
__device__ float2 g_gabe[COUT];                         // per-channel (gamma*inv, beta-mean*ga)

// ============================ helpers ============================
__device__ __forceinline__ uint32_t smem_u32(const void* p) {
    uint32_t a;
    asm("{ .reg .u64 t; cvta.to.shared.u64 t, %1; cvt.u32.u64 %0, t; }" : "=r"(a) : "l"(p));
    return a;
}
__device__ __forceinline__ void ldsm_x4(uint32_t& r0, uint32_t& r1, uint32_t& r2, uint32_t& r3,
                                        uint32_t addr) {
    asm volatile("ldmatrix.sync.aligned.m8n8.x4.shared.b16 {%0,%1,%2,%3}, [%4];"
                 : "=r"(r0), "=r"(r1), "=r"(r2), "=r"(r3) : "r"(addr));
}
__device__ __forceinline__ void ldsm_x4_t(uint32_t& r0, uint32_t& r1, uint32_t& r2, uint32_t& r3,
                                          uint32_t addr) {
    asm volatile("ldmatrix.sync.aligned.m8n8.x4.trans.shared.b16 {%0,%1,%2,%3}, [%4];"
                 : "=r"(r0), "=r"(r1), "=r"(r2), "=r"(r3) : "r"(addr));
}
__device__ __forceinline__ void mma16816(float* d, const uint32_t* a, uint32_t b0, uint32_t b1) {
    asm volatile("mma.sync.aligned.m16n8k16.row.col.f32.f16.f16.f32 "
                 "{%0,%1,%2,%3}, {%4,%5,%6,%7}, {%8,%9}, {%0,%1,%2,%3};"
                 : "+f"(d[0]), "+f"(d[1]), "+f"(d[2]), "+f"(d[3])
                 : "r"(a[0]), "r"(a[1]), "r"(a[2]), "r"(a[3]), "r"(b0), "r"(b1));
}

// ============================ kernel 0: init ============================
struct LCGTab { unsigned A[21]; unsigned C[21]; };
__host__ __device__ constexpr LCGTab make_tab() {
    LCGTab t{};
    unsigned a = 65539u, c = 1u;
    for (int j = 0; j < 21; j++) {
        t.A[j] = a; t.C[j] = c;
        unsigned c2 = a * c + c;
        a = a * a; c = c2;
    }
    return t;
}
__global__ void k_init(const float* __restrict__ w) {
    constexpr LCGTab T = make_tab();
    int i = blockIdx.x * blockDim.x + threadIdx.x;   // 0 .. 1048575
    unsigned n = (unsigned)i + 1u;
    unsigned rA = 1u, rC = 0u;
    #pragma unroll
    for (int j = 0; j < 21; j++) {
        if ((n >> j) & 1u) { rA = T.A[j] * rA; rC = T.A[j] * rC + T.C[j]; }
    }
    unsigned seed = rA * 12345u + rC;
    g_noise[i] = (float)seed * (float)(0.1 / 4294967295.0);

    if (i < COUT * KTOT) g_w[i] = __float2half_rn(w[i]);
    if (i < CIN * CIN)   g_C[i] = 0.0f;
    if (i < CIN)         g_S[i] = 0.0f;
}

// ============================ kernel 1: stats (C = A^T A, S = col sums) ============================
// grid (4, 64): blockIdx.x = tile (ti=bx>>1 over rows, tj=bx&1 over cols of C),
// blockIdx.y = 2048-pixel m-chunk. A = relu(x+noise) fp16 staged [c][m].
// Diagonal tiles also accumulate S. Output via fp32 atomicAdd into g_C / g_S.
#define ST_STRIDE 136
#define ST_TILE_B 34816             // 128 * 136 halves * 2
#define ST_TOTAL  69632

__global__ void __launch_bounds__(256, 2) k_stats(const float* __restrict__ x) {
    extern __shared__ char smem[];
    __half* smA1 = (__half*)smem;
    __half* smA2 = (__half*)(smem + ST_TILE_B);
    uint32_t a1u = smem_u32(smA1);
    uint32_t a2u = smem_u32(smA2);

    int tid = threadIdx.x, warp = tid >> 5, lane = tid & 31;
    int ti = blockIdx.x >> 1, tj = blockIdx.x & 1;
    bool diag = (ti == tj);
    int mchunk = blockIdx.y;            // 0..63
    int b = mchunk >> 1;
    int hwbase = (mchunk & 1) * 2048;

    int mw = (warp >> 2) * 64;          // warp ci offset
    int nw = (warp & 3) * 32;           // warp cj offset
    int g = lane >> 2, t = lane & 3;

    float acc[16][4];
    #pragma unroll
    for (int i = 0; i < 16; i++)
        #pragma unroll
        for (int j = 0; j < 4; j++) acc[i][j] = 0.0f;
    float ssum[16];
    #pragma unroll
    for (int r = 0; r < 16; r++) ssum[r] = 0.0f;

    // a-frag (non-trans, [ci][m] row-major): slots {r0-7/k0-7, r8-15/k0-7, r0-7/k8+, r8-15/k8+}
    uint32_t aaddr = a1u + (uint32_t)((mw + (lane & 15)) * ST_STRIDE + (lane >> 4) * 8) * 2u;
    // b-frag: same mapping as validated k_gemm B pattern
    uint32_t bbase = (diag ? a1u : a2u)
        + (uint32_t)((nw + (lane & 7) + ((lane >> 4) << 3)) * ST_STRIDE
                     + ((lane >> 3) & 1) * 8) * 2u;

    for (int sb = 0; sb < 16; sb++) {
        __syncthreads();                 // prev MMA reads done before restage
        int hw0 = hwbase + sb * 128;
        // stage smA1: channels ti*128 + warp*16 + r, 128 m per row
        #pragma unroll
        for (int r = 0; r < 16; r++) {
            int c = ti * 128 + warp * 16 + r;
            float4 xv = *(const float4*)(x + ((size_t)(b * CIN + c)) * HWSZ + hw0 + lane * 4);
            float4 nv = *(const float4*)(g_noise + (size_t)c * HWSZ + hw0 + lane * 4);
            float v0 = fmaxf(xv.x + nv.x, 0.0f);
            float v1 = fmaxf(xv.y + nv.y, 0.0f);
            float v2 = fmaxf(xv.z + nv.z, 0.0f);
            float v3 = fmaxf(xv.w + nv.w, 0.0f);
            if (diag) ssum[r] += (v0 + v1) + (v2 + v3);
            __half2 h01 = __floats2half2_rn(v0, v1);
            __half2 h23 = __floats2half2_rn(v2, v3);
            uint2 pack;
            pack.x = *(uint32_t*)&h01;
            pack.y = *(uint32_t*)&h23;
            *(uint2*)(smA1 + (warp * 16 + r) * ST_STRIDE + lane * 4) = pack;
        }
        if (!diag) {
            #pragma unroll
            for (int r = 0; r < 16; r++) {
                int c = tj * 128 + warp * 16 + r;
                float4 xv = *(const float4*)(x + ((size_t)(b * CIN + c)) * HWSZ + hw0 + lane * 4);
                float4 nv = *(const float4*)(g_noise + (size_t)c * HWSZ + hw0 + lane * 4);
                __half2 h01 = __floats2half2_rn(fmaxf(xv.x + nv.x, 0.0f), fmaxf(xv.y + nv.y, 0.0f));
                __half2 h23 = __floats2half2_rn(fmaxf(xv.z + nv.z, 0.0f), fmaxf(xv.w + nv.w, 0.0f));
                uint2 pack;
                pack.x = *(uint32_t*)&h01;
                pack.y = *(uint32_t*)&h23;
                *(uint2*)(smA2 + (warp * 16 + r) * ST_STRIDE + lane * 4) = pack;
            }
        }
        __syncthreads();

        // MMA: reduction dim = m (128 = 8 k-steps)
        #pragma unroll
        for (int ks = 0; ks < 8; ks++) {
            uint32_t afr[4][4];
            #pragma unroll
            for (int mi = 0; mi < 4; mi++)
                ldsm_x4(afr[mi][0], afr[mi][1], afr[mi][2], afr[mi][3],
                        aaddr + (uint32_t)(mi * 16 * ST_STRIDE + ks * 16) * 2u);
            uint32_t bfr[2][4];
            #pragma unroll
            for (int nip = 0; nip < 2; nip++)
                ldsm_x4(bfr[nip][0], bfr[nip][1], bfr[nip][2], bfr[nip][3],
                        bbase + (uint32_t)(nip * 16 * ST_STRIDE + ks * 16) * 2u);
            #pragma unroll
            for (int mi = 0; mi < 4; mi++)
                #pragma unroll
                for (int ni = 0; ni < 4; ni++)
                    mma16816(acc[mi * 4 + ni], afr[mi],
                             bfr[ni >> 1][(ni & 1) * 2], bfr[ni >> 1][(ni & 1) * 2 + 1]);
        }
    }

    // reduce C tile into global
    #pragma unroll
    for (int mi = 0; mi < 4; mi++)
        #pragma unroll
        for (int ni = 0; ni < 4; ni++) {
            int ci = ti * 128 + mw + mi * 16 + g;
            int cj = tj * 128 + nw + ni * 8 + t * 2;
            atomicAdd(&g_C[ci * CIN + cj],             acc[mi * 4 + ni][0]);
            atomicAdd(&g_C[ci * CIN + cj + 1],         acc[mi * 4 + ni][1]);
            atomicAdd(&g_C[(ci + 8) * CIN + cj],       acc[mi * 4 + ni][2]);
            atomicAdd(&g_C[(ci + 8) * CIN + cj + 1],   acc[mi * 4 + ni][3]);
        }
    if (diag) {
        #pragma unroll
        for (int r = 0; r < 16; r++) {
            float v = ssum[r];
            #pragma unroll
            for (int off = 16; off; off >>= 1)
                v += __shfl_xor_sync(0xFFFFFFFFu, v, off);
            if (lane == 0) atomicAdd(&g_S[ti * 128 + warp * 16 + r], v);
        }
    }
}

// ============================ kernel 2: finalize BN constants ============================
// Per o: mean = (w_o.S)/N, Ey2 = (w_o^T C w_o)/N via u = w_o^T C (coalesced C reads).
__global__ void k_fin(const float* __restrict__ gamma, const float* __restrict__ beta) {
    __shared__ float smw[4][256];
    __shared__ float red[256];
    int tid = threadIdx.x;
    int o0 = blockIdx.x * 4;
    #pragma unroll
    for (int q = 0; q < 4; q++)
        smw[q][tid] = __half2float(g_w[(size_t)(o0 + q) * KTOT + tid]);
    __syncthreads();

    float u[4] = {0.0f, 0.0f, 0.0f, 0.0f};
    #pragma unroll 8
    for (int r = 0; r < 256; r++) {
        float cr = g_C[r * CIN + tid];
        #pragma unroll
        for (int q = 0; q < 4; q++) u[q] += smw[q][r] * cr;
    }
    float Sc = g_S[tid];

    for (int q = 0; q < 4; q++) {
        red[tid] = u[q] * smw[q][tid];
        __syncthreads();
        for (int s = 128; s > 0; s >>= 1) {
            if (tid < s) red[tid] += red[tid + s];
            __syncthreads();
        }
        float ssq = red[0];              // valid in all threads after syncs
        __syncthreads();
        red[tid] = smw[q][tid] * Sc;
        __syncthreads();
        for (int s = 128; s > 0; s >>= 1) {
            if (tid < s) red[tid] += red[tid + s];
            __syncthreads();
        }
        if (tid == 0) {
            float mean = red[0] * (1.0f / NPIX);
            float ey2  = ssq   * (1.0f / NPIX);
            float var  = ey2 - mean * mean;
            float inv  = rsqrtf(var + 1e-5f);
            float ga = gamma[o0 + q] * inv;
            float be = beta[o0 + q] - mean * ga;
            g_gabe[o0 + q] = make_float2(ga, be);
        }
        __syncthreads();
    }
}

// ============================ kernel 3: GEMM + fused normalize -> out ============================
// CTA: 128 m-pixels x all 512 out-channels. A full-K resident (x read once).
// B single-buffer per phase (R8 style). Epilogue: y*ga+be stored fp32 straight to out.
#define SMA_OFF    0                       // [256 k][136 m] half = 69632 B
#define SMB_OFF    69632                   // [128 n][72 k] half = 18432 B
#define SM_TOTAL   88064
#define SMA_STRIDE 136
#define SMB_STRIDE 72

__global__ void __launch_bounds__(256, 2) k_gemm(const float* __restrict__ x,
                                                 float* __restrict__ out) {
    extern __shared__ char smem[];
    __half* smA = (__half*)(smem + SMA_OFF);
    __half* smB = (__half*)(smem + SMB_OFF);
    uint32_t smA_u = smem_u32(smA);
    uint32_t smB_u = smem_u32(smB);

    int tid = threadIdx.x, warp = tid >> 5, lane = tid & 31;
    int mtile = blockIdx.x;            // 0..1023
    int b   = mtile >> 5;
    int hw0 = (mtile & 31) << 7;

    int mw = (warp >> 2) * 64;
    int nw = (warp & 3) * 32;
    int cl = warp * 8;
    int brow = tid & 127, bpart = tid >> 7;

    float acc[16][4];
    #pragma unroll
    for (int i = 0; i < 16; i++)
        #pragma unroll
        for (int j = 0; j < 4; j++) acc[i][j] = 0.0f;

    uint32_t aaddr = smA_u + (uint32_t)(((lane & 7) + ((lane >> 4) << 3)) * SMA_STRIDE
                                        + mw + ((lane >> 3) & 1) * 8) * 2u;
    uint32_t blane = smB_u + (uint32_t)((nw + (lane & 7) + ((lane >> 4) << 3)) * SMB_STRIDE
                                        + ((lane >> 3) & 1) * 8) * 2u;
    int g = lane >> 2, t = lane & 3;

    for (int nt = 0; nt < 4; nt++) {
        for (int kc = 0; kc < 4; kc++) {
            if (nt == 0) {
                #pragma unroll
                for (int r = 0; r < 8; r++) {
                    int c = kc * 64 + cl + r;
                    float4 xv = *(const float4*)(x + ((size_t)(b * CIN + c)) * HWSZ + hw0 + lane * 4);
                    float4 nv = *(const float4*)(g_noise + (size_t)c * HWSZ + hw0 + lane * 4);
                    __half2 h01 = __floats2half2_rn(fmaxf(xv.x + nv.x, 0.0f), fmaxf(xv.y + nv.y, 0.0f));
                    __half2 h23 = __floats2half2_rn(fmaxf(xv.z + nv.z, 0.0f), fmaxf(xv.w + nv.w, 0.0f));
                    uint2 pack;
                    pack.x = *(uint32_t*)&h01;
                    pack.y = *(uint32_t*)&h23;
                    *(uint2*)(smA + c * SMA_STRIDE + lane * 4) = pack;
                }
            }
            {   // B tile (nt, kc) from L2-resident weights
                const uint4* src = (const uint4*)(g_w + (size_t)(nt * 128 + brow) * KTOT
                                                  + kc * 64 + bpart * 32);
                uint4* dst = (uint4*)(smB + brow * SMB_STRIDE + bpart * 32);
                dst[0] = src[0]; dst[1] = src[1]; dst[2] = src[2]; dst[3] = src[3];
            }
            __syncthreads();

            uint32_t abase = aaddr + (uint32_t)(kc * 64 * SMA_STRIDE) * 2u;
            #pragma unroll
            for (int ks = 0; ks < 4; ks++) {
                uint32_t afr[4][4];
                #pragma unroll
                for (int mi = 0; mi < 4; mi++)
                    ldsm_x4_t(afr[mi][0], afr[mi][1], afr[mi][2], afr[mi][3],
                              abase + (uint32_t)(ks * 16 * SMA_STRIDE + mi * 16) * 2u);
                uint32_t bfr[2][4];
                #pragma unroll
                for (int nip = 0; nip < 2; nip++)
                    ldsm_x4(bfr[nip][0], bfr[nip][1], bfr[nip][2], bfr[nip][3],
                            blane + (uint32_t)(nip * 16 * SMB_STRIDE + ks * 16) * 2u);
                #pragma unroll
                for (int mi = 0; mi < 4; mi++)
                    #pragma unroll
                    for (int ni = 0; ni < 4; ni++)
                        mma16816(acc[mi * 4 + ni], afr[mi],
                                 bfr[ni >> 1][(ni & 1) * 2], bfr[ni >> 1][(ni & 1) * 2 + 1]);
            }
            __syncthreads();
        }

        // ---- epilogue: normalize in-register, store fp32 directly to out ----
        float2 gb[8];
        #pragma unroll
        for (int ni = 0; ni < 4; ni++) {
            int n = nt * 128 + nw + ni * 8 + t * 2;
            gb[ni * 2]     = g_gabe[n];
            gb[ni * 2 + 1] = g_gabe[n + 1];
        }
        #pragma unroll
        for (int mi = 0; mi < 4; mi++)
            #pragma unroll
            for (int ni = 0; ni < 4; ni++) {
                float c0 = acc[mi * 4 + ni][0], c1 = acc[mi * 4 + ni][1];
                float c2 = acc[mi * 4 + ni][2], c3 = acc[mi * 4 + ni][3];
                acc[mi * 4 + ni][0] = 0.0f; acc[mi * 4 + ni][1] = 0.0f;
                acc[mi * 4 + ni][2] = 0.0f; acc[mi * 4 + ni][3] = 0.0f;
                int n0 = nt * 128 + nw + ni * 8 + t * 2;
                int m0 = mw + mi * 16 + g;
                float2 q0 = gb[ni * 2], q1 = gb[ni * 2 + 1];
                size_t base0 = ((size_t)(b * COUT + n0)) * HWSZ + hw0 + m0;
                size_t base1 = base0 + HWSZ;
                out[base0]     = c0 * q0.x + q0.y;
                out[base0 + 8] = c2 * q0.x + q0.y;
                out[base1]     = c1 * q1.x + q1.y;
                out[base1 + 8] = c3 * q1.x + q1.y;
            }
        // next nt's smB staging is ordered by the post-MMA __syncthreads above
    }
}

// ============================ launcher ============================
extern "C" void kernel_launch(void* const* d_in, const int* in_sizes, int n_in,
                              void* d_out, int out_size) {
    const float* x     = (const float*)d_in[0];
    const float* w     = (const float*)d_in[1];
    // d_in[2] = conv_b: exactly cancelled by BatchNorm mean subtraction.
    const float* gamma = (const float*)d_in[3];
    const float* beta  = (const float*)d_in[4];
    float* out = (float*)d_out;

    cudaFuncSetAttribute(k_stats, cudaFuncAttributeMaxDynamicSharedMemorySize, ST_TOTAL);
    cudaFuncSetAttribute(k_gemm,  cudaFuncAttributeMaxDynamicSharedMemorySize, SM_TOTAL);

    k_init<<<4096, 256>>>(w);                      // noise + fp16 W + zero C/S
    k_stats<<<dim3(4, 64), 256, ST_TOTAL>>>(x);    // C = A^T A, S = col sums
    k_fin<<<128, 256>>>(gamma, beta);              // (ga, be) per channel
    k_gemm<<<1024, 256, SM_TOTAL>>>(x, out);       // y -> normalize -> out (fp32)
}

// round 12
// speedup vs baseline: 1.0260x; 1.0260x over previous
#include <cuda_runtime.h>
#include <cuda_fp16.h>
#include <cstdint>

// ============================ problem sizes ============================
#define BB    32
#define CIN   256
#define COUT  512
#define HWSZ  4096                  // 64*64
#define KTOT  256
#define NPIX  131072.0f             // B*H*W per channel

// ============================ device scratch ============================
__device__ __align__(128) float  g_noise[CIN * HWSZ];           // 4 MB
__device__ __align__(128) __half g_w[COUT * KTOT];              // 256 KB [o][c]
__device__ __align__(128) __half g_a[(size_t)131072 * KTOT];    // 67 MB  [mtile][k][128m]
__device__ __align__(128) float  g_C[CIN * CIN];                // 256 KB  A^T A
__device__ float  g_S[CIN];                                     // column sums of A
__device__ float2 g_gabe[COUT];                                 // (gamma*inv, beta-mean*ga)

// ============================ helpers ============================
__device__ __forceinline__ uint32_t smem_u32(const void* p) {
    uint32_t a;
    asm("{ .reg .u64 t; cvta.to.shared.u64 t, %1; cvt.u32.u64 %0, t; }" : "=r"(a) : "l"(p));
    return a;
}
__device__ __forceinline__ void ldsm_x4(uint32_t& r0, uint32_t& r1, uint32_t& r2, uint32_t& r3,
                                        uint32_t addr) {
    asm volatile("ldmatrix.sync.aligned.m8n8.x4.shared.b16 {%0,%1,%2,%3}, [%4];"
                 : "=r"(r0), "=r"(r1), "=r"(r2), "=r"(r3) : "r"(addr));
}
__device__ __forceinline__ void ldsm_x4_t(uint32_t& r0, uint32_t& r1, uint32_t& r2, uint32_t& r3,
                                          uint32_t addr) {
    asm volatile("ldmatrix.sync.aligned.m8n8.x4.trans.shared.b16 {%0,%1,%2,%3}, [%4];"
                 : "=r"(r0), "=r"(r1), "=r"(r2), "=r"(r3) : "r"(addr));
}
__device__ __forceinline__ void mma16816(float* d, const uint32_t* a, uint32_t b0, uint32_t b1) {
    asm volatile("mma.sync.aligned.m16n8k16.row.col.f32.f16.f16.f32 "
                 "{%0,%1,%2,%3}, {%4,%5,%6,%7}, {%8,%9}, {%0,%1,%2,%3};"
                 : "+f"(d[0]), "+f"(d[1]), "+f"(d[2]), "+f"(d[3])
                 : "r"(a[0]), "r"(a[1]), "r"(a[2]), "r"(a[3]), "r"(b0), "r"(b1));
}
__device__ __forceinline__ void cp_async16(uint32_t smem_dst, const void* gsrc) {
    asm volatile("cp.async.cg.shared.global [%0], [%1], 16;"
                 :: "r"(smem_dst), "l"(gsrc) : "memory");
}
#define CP_COMMIT() asm volatile("cp.async.commit_group;" ::: "memory")
#define CP_WAIT0()  asm volatile("cp.async.wait_group 0;" ::: "memory")
#define CP_WAIT1()  asm volatile("cp.async.wait_group 1;" ::: "memory")

// ============================ kernel 0: init ============================
struct LCGTab { unsigned A[21]; unsigned C[21]; };
__host__ __device__ constexpr LCGTab make_tab() {
    LCGTab t{};
    unsigned a = 65539u, c = 1u;
    for (int j = 0; j < 21; j++) {
        t.A[j] = a; t.C[j] = c;
        unsigned c2 = a * c + c;
        a = a * a; c = c2;
    }
    return t;
}
__global__ void k_init(const float* __restrict__ w) {
    constexpr LCGTab T = make_tab();
    int i = blockIdx.x * blockDim.x + threadIdx.x;   // 0 .. 1048575
    unsigned n = (unsigned)i + 1u;
    unsigned rA = 1u, rC = 0u;
    #pragma unroll
    for (int j = 0; j < 21; j++) {
        if ((n >> j) & 1u) { rA = T.A[j] * rA; rC = T.A[j] * rC + T.C[j]; }
    }
    unsigned seed = rA * 12345u + rC;
    g_noise[i] = (float)seed * (float)(0.1 / 4294967295.0);

    if (i < COUT * KTOT) g_w[i] = __float2half_rn(w[i]);
    if (i < CIN * CIN)   g_C[i] = 0.0f;
    if (i < CIN)         g_S[i] = 0.0f;
}

// ============================ kernel 1: prep A = relu(x+noise) fp16 ============================
// Layout g_a[mtile][k][128 m]. Block = one channel c, 1024 m. Also accumulates S[c].
__global__ void __launch_bounds__(256) k_prep(const float* __restrict__ x) {
    __shared__ float red[8];
    int tid = threadIdx.x, warp = tid >> 5, lane = tid & 31;
    int c = blockIdx.x >> 7;
    int m = ((blockIdx.x & 127) << 10) + tid * 4;
    int batch = m >> 12, hw = m & 4095;

    float4 xv = *(const float4*)(x + ((size_t)(batch * CIN + c)) * HWSZ + hw);
    float4 nv = *(const float4*)(g_noise + (size_t)c * HWSZ + hw);
    float v0 = fmaxf(xv.x + nv.x, 0.0f);
    float v1 = fmaxf(xv.y + nv.y, 0.0f);
    float v2 = fmaxf(xv.z + nv.z, 0.0f);
    float v3 = fmaxf(xv.w + nv.w, 0.0f);

    __half2 h01 = __floats2half2_rn(v0, v1);
    __half2 h23 = __floats2half2_rn(v2, v3);
    uint2 pack;
    pack.x = *(uint32_t*)&h01;
    pack.y = *(uint32_t*)&h23;
    int mtile = m >> 7, mloc = m & 127;
    *(uint2*)(g_a + (size_t)mtile * 32768 + c * 128 + mloc) = pack;

    float s = (v0 + v1) + (v2 + v3);
    #pragma unroll
    for (int off = 16; off; off >>= 1) s += __shfl_xor_sync(0xFFFFFFFFu, s, off);
    if (lane == 0) red[warp] = s;
    __syncthreads();
    if (tid == 0) {
        float tot = 0.0f;
        #pragma unroll
        for (int i = 0; i < 8; i++) tot += red[i];
        atomicAdd(&g_S[c], tot);
    }
}

// ============================ kernel 2: stats C = A^T A ============================
// grid (4, 64): bx -> (ti,tj) C tile, by -> 2048-m chunk (32 slabs of 64 m).
// cp.async double-buffered slabs; MMA reduction over m. fp32 atomics into g_C.
#define ST_STRIDE 72
#define ST_BUF_B  36864                    // 256 rows * 144 B
#define ST_TOTAL  73728

__global__ void __launch_bounds__(256, 2) k_stats() {
    extern __shared__ char smem[];
    uint32_t sb_u = smem_u32(smem);

    int tid = threadIdx.x, warp = tid >> 5, lane = tid & 31;
    int ti = blockIdx.x >> 1, tj = blockIdx.x & 1;
    bool diag = (ti == tj);
    int rows = diag ? 128 : 256;
    int chunk = blockIdx.y;

    int mw = (warp >> 2) * 64;
    int nw = (warp & 3) * 32;
    int g = lane >> 2, t = lane & 3;

    float acc[16][4];
    #pragma unroll
    for (int i = 0; i < 16; i++)
        #pragma unroll
        for (int j = 0; j < 4; j++) acc[i][j] = 0.0f;

    uint32_t aoff = (uint32_t)((mw + (lane & 15)) * ST_STRIDE + (lane >> 4) * 8) * 2u;
    uint32_t boff_frag = (uint32_t)((nw + (lane & 7) + ((lane >> 4) << 3)) * ST_STRIDE
                                    + ((lane >> 3) & 1) * 8) * 2u;

    // stage one slab: rows * 8 16B units (64 m per row) into buf
    auto issue = [&](int sb, int buf) {
        int mtile = chunk * 16 + (sb >> 1);
        int m0 = (sb & 1) * 64;
        uint32_t dstb = sb_u + (uint32_t)buf * ST_BUF_B;
        const __half* srcb = g_a + (size_t)mtile * 32768 + m0;
        for (int u = tid; u < rows * 8; u += 256) {
            int r = u >> 3, part = u & 7;
            int krow = (r < 128) ? ti * 128 + r : tj * 128 + (r - 128);
            cp_async16(dstb + (uint32_t)(r * 144 + part * 16),
                       srcb + (size_t)krow * 128 + part * 8);
        }
        CP_COMMIT();
    };

    issue(0, 0);
    for (int sb = 0; sb < 32; sb++) {
        if (sb + 1 < 32) { issue(sb + 1, (sb + 1) & 1); CP_WAIT1(); }
        else             { CP_WAIT0(); }
        __syncthreads();

        uint32_t bufb = sb_u + (uint32_t)((sb & 1) * ST_BUF_B);
        uint32_t aaddr = bufb + aoff;
        uint32_t bbase = bufb + (diag ? 0u : (uint32_t)(128 * 144)) + boff_frag;
        #pragma unroll
        for (int ks = 0; ks < 4; ks++) {
            uint32_t afr[4][4];
            #pragma unroll
            for (int mi = 0; mi < 4; mi++)
                ldsm_x4(afr[mi][0], afr[mi][1], afr[mi][2], afr[mi][3],
                        aaddr + (uint32_t)(mi * 16 * ST_STRIDE + ks * 16) * 2u);
            uint32_t bfr[2][4];
            #pragma unroll
            for (int nip = 0; nip < 2; nip++)
                ldsm_x4(bfr[nip][0], bfr[nip][1], bfr[nip][2], bfr[nip][3],
                        bbase + (uint32_t)(nip * 16 * ST_STRIDE + ks * 16) * 2u);
            #pragma unroll
            for (int mi = 0; mi < 4; mi++)
                #pragma unroll
                for (int ni = 0; ni < 4; ni++)
                    mma16816(acc[mi * 4 + ni], afr[mi],
                             bfr[ni >> 1][(ni & 1) * 2], bfr[ni >> 1][(ni & 1) * 2 + 1]);
        }
        __syncthreads();
    }

    #pragma unroll
    for (int mi = 0; mi < 4; mi++)
        #pragma unroll
        for (int ni = 0; ni < 4; ni++) {
            int ci = ti * 128 + mw + mi * 16 + g;
            int cj = tj * 128 + nw + ni * 8 + t * 2;
            atomicAdd(&g_C[ci * CIN + cj],           acc[mi * 4 + ni][0]);
            atomicAdd(&g_C[ci * CIN + cj + 1],       acc[mi * 4 + ni][1]);
            atomicAdd(&g_C[(ci + 8) * CIN + cj],     acc[mi * 4 + ni][2]);
            atomicAdd(&g_C[(ci + 8) * CIN + cj + 1], acc[mi * 4 + ni][3]);
        }
}

// ============================ kernel 3: finalize BN constants ============================
__global__ void k_fin(const float* __restrict__ gamma, const float* __restrict__ beta) {
    __shared__ float smw[4][256];
    __shared__ float red[256];
    int tid = threadIdx.x;
    int o0 = blockIdx.x * 4;
    #pragma unroll
    for (int q = 0; q < 4; q++)
        smw[q][tid] = __half2float(g_w[(size_t)(o0 + q) * KTOT + tid]);
    __syncthreads();

    float u[4] = {0.0f, 0.0f, 0.0f, 0.0f};
    #pragma unroll 8
    for (int r = 0; r < 256; r++) {
        float cr = g_C[r * CIN + tid];
        #pragma unroll
        for (int q = 0; q < 4; q++) u[q] += smw[q][r] * cr;
    }
    float Sc = g_S[tid];

    for (int q = 0; q < 4; q++) {
        red[tid] = u[q] * smw[q][tid];
        __syncthreads();
        for (int s = 128; s > 0; s >>= 1) {
            if (tid < s) red[tid] += red[tid + s];
            __syncthreads();
        }
        float ssq = red[0];
        __syncthreads();
        red[tid] = smw[q][tid] * Sc;
        __syncthreads();
        for (int s = 128; s > 0; s >>= 1) {
            if (tid < s) red[tid] += red[tid + s];
            __syncthreads();
        }
        if (tid == 0) {
            float mean = red[0] * (1.0f / NPIX);
            float ey2  = ssq   * (1.0f / NPIX);
            float var  = ey2 - mean * mean;
            float inv  = rsqrtf(var + 1e-5f);
            float ga = gamma[o0 + q] * inv;
            float be = beta[o0 + q] - mean * ga;
            g_gabe[o0 + q] = make_float2(ga, be);
        }
        __syncthreads();
    }
}

// ============================ kernel 4: GEMM + fused normalize -> out ============================
// A prefab fp16, full-K resident via one cp.async burst (FIX: 16 parts/row = full 64KB).
// B per-phase plain loads. Epilogue: coalesced fp32 stores via 4x 32-n transpose passes.
#define SMA_OFF    0                       // [256 k][136 m] half = 69632 B
#define SMB_OFF    69632                   // 18432 B (B tile / fp32 transpose buffer)
#define SM_TOTAL   88064
#define SMA_STRIDE 136
#define SMB_STRIDE 72
#define T_STRIDE   132                     // floats; 32n x 132 x 4B = 16896 B

__global__ void __launch_bounds__(256, 2) k_gemm(float* __restrict__ out) {
    extern __shared__ char smem[];
    __half* smB = (__half*)(smem + SMB_OFF);
    uint32_t smA_u = smem_u32(smem);
    uint32_t smB_u = smem_u32(smB);

    int tid = threadIdx.x, warp = tid >> 5, lane = tid & 31;
    int mtile = blockIdx.x;            // 0..1023
    int b   = mtile >> 5;
    int hw0 = (mtile & 31) << 7;

    int mw = (warp >> 2) * 64;
    int nw = (warp & 3) * 32;
    int brow = tid & 127, bpart = tid >> 7;
    int g = lane >> 2, t = lane & 3;

    // prologue: cp.async full A tile (256 rows x 128 m fp16 = 256 B/row -> 16 parts)
    {
        const __half* srcb = g_a + (size_t)mtile * 32768;
        #pragma unroll
        for (int it = 0; it < 16; it++) {
            int u = it * 256 + tid;
            int r = u >> 4, part = u & 15;
            cp_async16(smA_u + (uint32_t)(r * 272 + part * 16),
                       srcb + (size_t)r * 128 + part * 8);
        }
        CP_COMMIT();
    }

    float acc[16][4];
    #pragma unroll
    for (int i = 0; i < 16; i++)
        #pragma unroll
        for (int j = 0; j < 4; j++) acc[i][j] = 0.0f;

    uint32_t aaddr = smA_u + (uint32_t)(((lane & 7) + ((lane >> 4) << 3)) * SMA_STRIDE
                                        + mw + ((lane >> 3) & 1) * 8) * 2u;
    uint32_t blane = smB_u + (uint32_t)((nw + (lane & 7) + ((lane >> 4) << 3)) * SMB_STRIDE
                                        + ((lane >> 3) & 1) * 8) * 2u;

    for (int nt = 0; nt < 4; nt++) {
        for (int kc = 0; kc < 4; kc++) {
            {   // B tile (nt, kc) from L2-resident weights
                const uint4* src = (const uint4*)(g_w + (size_t)(nt * 128 + brow) * KTOT
                                                  + kc * 64 + bpart * 32);
                uint4* dst = (uint4*)(smB + brow * SMB_STRIDE + bpart * 32);
                dst[0] = src[0]; dst[1] = src[1]; dst[2] = src[2]; dst[3] = src[3];
            }
            if (nt == 0 && kc == 0) CP_WAIT0();      // A tile resident
            __syncthreads();

            uint32_t abase = aaddr + (uint32_t)(kc * 64 * SMA_STRIDE) * 2u;
            #pragma unroll
            for (int ks = 0; ks < 4; ks++) {
                uint32_t afr[4][4];
                #pragma unroll
                for (int mi = 0; mi < 4; mi++)
                    ldsm_x4_t(afr[mi][0], afr[mi][1], afr[mi][2], afr[mi][3],
                              abase + (uint32_t)(ks * 16 * SMA_STRIDE + mi * 16) * 2u);
                uint32_t bfr[2][4];
                #pragma unroll
                for (int nip = 0; nip < 2; nip++)
                    ldsm_x4(bfr[nip][0], bfr[nip][1], bfr[nip][2], bfr[nip][3],
                            blane + (uint32_t)(nip * 16 * SMB_STRIDE + ks * 16) * 2u);
                #pragma unroll
                for (int mi = 0; mi < 4; mi++)
                    #pragma unroll
                    for (int ni = 0; ni < 4; ni++)
                        mma16816(acc[mi * 4 + ni], afr[mi],
                                 bfr[ni >> 1][(ni & 1) * 2], bfr[ni >> 1][(ni & 1) * 2 + 1]);
            }
            __syncthreads();
        }

        // ---- epilogue: normalize + coalesced fp32 stores via 32-n transpose passes ----
        float2 gb[8];
        #pragma unroll
        for (int ni = 0; ni < 4; ni++) {
            int n = nt * 128 + nw + ni * 8 + t * 2;
            gb[ni * 2]     = g_gabe[n];
            gb[ni * 2 + 1] = g_gabe[n + 1];
        }
        float* smT = (float*)(smem + SMB_OFF);
        #pragma unroll
        for (int p = 0; p < 4; p++) {
            if ((warp & 3) == p) {
                #pragma unroll
                for (int mi = 0; mi < 4; mi++)
                    #pragma unroll
                    for (int ni = 0; ni < 4; ni++) {
                        int m0 = mw + mi * 16 + g;
                        int nl = ni * 8 + t * 2;
                        float2 q0 = gb[ni * 2], q1 = gb[ni * 2 + 1];
                        smT[nl * T_STRIDE + m0]           = acc[mi * 4 + ni][0] * q0.x + q0.y;
                        smT[(nl + 1) * T_STRIDE + m0]     = acc[mi * 4 + ni][1] * q1.x + q1.y;
                        smT[nl * T_STRIDE + m0 + 8]       = acc[mi * 4 + ni][2] * q0.x + q0.y;
                        smT[(nl + 1) * T_STRIDE + m0 + 8] = acc[mi * 4 + ni][3] * q1.x + q1.y;
                        acc[mi * 4 + ni][0] = 0.0f; acc[mi * 4 + ni][1] = 0.0f;
                        acc[mi * 4 + ni][2] = 0.0f; acc[mi * 4 + ni][3] = 0.0f;
                    }
            }
            __syncthreads();
            #pragma unroll
            for (int i = 0; i < 4; i++) {
                int row = warp * 4 + i;
                float4 v = *(float4*)(smT + row * T_STRIDE + lane * 4);
                __stcs((float4*)(out + ((size_t)(b * COUT + nt * 128 + p * 32 + row)) * HWSZ
                                 + hw0 + lane * 4), v);
            }
            __syncthreads();
        }
    }
}

// ============================ launcher ============================
extern "C" void kernel_launch(void* const* d_in, const int* in_sizes, int n_in,
                              void* d_out, int out_size) {
    const float* x     = (const float*)d_in[0];
    const float* w     = (const float*)d_in[1];
    // d_in[2] = conv_b: exactly cancelled by BatchNorm mean subtraction.
    const float* gamma = (const float*)d_in[3];
    const float* beta  = (const float*)d_in[4];
    float* out = (float*)d_out;

    cudaFuncSetAttribute(k_stats, cudaFuncAttributeMaxDynamicSharedMemorySize, ST_TOTAL);
    cudaFuncSetAttribute(k_gemm,  cudaFuncAttributeMaxDynamicSharedMemorySize, SM_TOTAL);

    k_init<<<4096, 256>>>(w);                      // noise + fp16 W + zero C/S
    k_prep<<<32768, 256>>>(x);                     // A = relu(x+noise) fp16 tiles + S
    k_stats<<<dim3(4, 64), 256, ST_TOTAL>>>();     // C = A^T A (cp.async pipelined)
    k_fin<<<128, 256>>>(gamma, beta);              // (ga, be) per channel
    k_gemm<<<1024, 256, SM_TOTAL>>>(out);          // y -> normalize -> out (coalesced)
}

// round 13
// speedup vs baseline: 1.1184x; 1.0900x over previous
#include <cuda_runtime.h>
#include <cuda_fp16.h>
#include <cstdint>

// ============================ problem sizes ============================
#define BB    32
#define CIN   256
#define COUT  512
#define HWSZ  4096                  // 64*64
#define KTOT  256
#define NPIX  131072.0f             // B*H*W per channel

// ============================ device scratch ============================
__device__ __align__(128) float  g_noise[CIN * HWSZ];           // 4 MB
__device__ __align__(128) __half g_w[COUT * KTOT];              // 256 KB [o][c]
__device__ __align__(128) __half g_a[(size_t)131072 * KTOT];    // 67 MB  [mtile][k][128m]
__device__ __align__(128) float  g_C[CIN * CIN];                // 256 KB  A^T A
__device__ float  g_S[CIN];                                     // column sums of A
__device__ float  g_ssq[COUT];                                  // w_o^T C w_o partials
__device__ float2 g_gabe[COUT];                                 // (gamma*inv, beta-mean*ga)

// ============================ helpers ============================
__device__ __forceinline__ uint32_t smem_u32(const void* p) {
    uint32_t a;
    asm("{ .reg .u64 t; cvta.to.shared.u64 t, %1; cvt.u32.u64 %0, t; }" : "=r"(a) : "l"(p));
    return a;
}
__device__ __forceinline__ void ldsm_x4(uint32_t& r0, uint32_t& r1, uint32_t& r2, uint32_t& r3,
                                        uint32_t addr) {
    asm volatile("ldmatrix.sync.aligned.m8n8.x4.shared.b16 {%0,%1,%2,%3}, [%4];"
                 : "=r"(r0), "=r"(r1), "=r"(r2), "=r"(r3) : "r"(addr));
}
__device__ __forceinline__ void ldsm_x4_t(uint32_t& r0, uint32_t& r1, uint32_t& r2, uint32_t& r3,
                                          uint32_t addr) {
    asm volatile("ldmatrix.sync.aligned.m8n8.x4.trans.shared.b16 {%0,%1,%2,%3}, [%4];"
                 : "=r"(r0), "=r"(r1), "=r"(r2), "=r"(r3) : "r"(addr));
}
__device__ __forceinline__ void mma16816(float* d, const uint32_t* a, uint32_t b0, uint32_t b1) {
    asm volatile("mma.sync.aligned.m16n8k16.row.col.f32.f16.f16.f32 "
                 "{%0,%1,%2,%3}, {%4,%5,%6,%7}, {%8,%9}, {%0,%1,%2,%3};"
                 : "+f"(d[0]), "+f"(d[1]), "+f"(d[2]), "+f"(d[3])
                 : "r"(a[0]), "r"(a[1]), "r"(a[2]), "r"(a[3]), "r"(b0), "r"(b1));
}
__device__ __forceinline__ void cp_async16(uint32_t smem_dst, const void* gsrc) {
    asm volatile("cp.async.cg.shared.global [%0], [%1], 16;"
                 :: "r"(smem_dst), "l"(gsrc) : "memory");
}
#define CP_COMMIT() asm volatile("cp.async.commit_group;" ::: "memory")
#define CP_WAIT0()  asm volatile("cp.async.wait_group 0;" ::: "memory")
#define CP_WAIT1()  asm volatile("cp.async.wait_group 1;" ::: "memory")

// ============================ kernel 0: init ============================
struct LCGTab { unsigned A[21]; unsigned C[21]; };
__host__ __device__ constexpr LCGTab make_tab() {
    LCGTab t{};
    unsigned a = 65539u, c = 1u;
    for (int j = 0; j < 21; j++) {
        t.A[j] = a; t.C[j] = c;
        unsigned c2 = a * c + c;
        a = a * a; c = c2;
    }
    return t;
}
__global__ void k_init(const float* __restrict__ w) {
    constexpr LCGTab T = make_tab();
    int i = blockIdx.x * blockDim.x + threadIdx.x;   // 0 .. 1048575
    unsigned n = (unsigned)i + 1u;
    unsigned rA = 1u, rC = 0u;
    #pragma unroll
    for (int j = 0; j < 21; j++) {
        if ((n >> j) & 1u) { rA = T.A[j] * rA; rC = T.A[j] * rC + T.C[j]; }
    }
    unsigned seed = rA * 12345u + rC;
    g_noise[i] = (float)seed * (float)(0.1 / 4294967295.0);

    if (i < COUT * KTOT) g_w[i] = __float2half_rn(w[i]);
    if (i < CIN * CIN)   g_C[i] = 0.0f;
    if (i < CIN)         g_S[i] = 0.0f;
    if (i < COUT)        g_ssq[i] = 0.0f;
}

// ============================ kernel 1: prep A = relu(x+noise) fp16 ============================
// Layout g_a[mtile][k][128 m]. Block = one channel c, 1024 m. Also accumulates S[c].
__global__ void __launch_bounds__(256) k_prep(const float* __restrict__ x) {
    __shared__ float red[8];
    int tid = threadIdx.x, warp = tid >> 5, lane = tid & 31;
    int c = blockIdx.x >> 7;
    int m = ((blockIdx.x & 127) << 10) + tid * 4;
    int batch = m >> 12, hw = m & 4095;

    float4 xv = *(const float4*)(x + ((size_t)(batch * CIN + c)) * HWSZ + hw);
    float4 nv = *(const float4*)(g_noise + (size_t)c * HWSZ + hw);
    float v0 = fmaxf(xv.x + nv.x, 0.0f);
    float v1 = fmaxf(xv.y + nv.y, 0.0f);
    float v2 = fmaxf(xv.z + nv.z, 0.0f);
    float v3 = fmaxf(xv.w + nv.w, 0.0f);

    __half2 h01 = __floats2half2_rn(v0, v1);
    __half2 h23 = __floats2half2_rn(v2, v3);
    uint2 pack;
    pack.x = *(uint32_t*)&h01;
    pack.y = *(uint32_t*)&h23;
    int mtile = m >> 7, mloc = m & 127;
    *(uint2*)(g_a + (size_t)mtile * 32768 + c * 128 + mloc) = pack;

    float s = (v0 + v1) + (v2 + v3);
    #pragma unroll
    for (int off = 16; off; off >>= 1) s += __shfl_xor_sync(0xFFFFFFFFu, s, off);
    if (lane == 0) red[warp] = s;
    __syncthreads();
    if (tid == 0) {
        float tot = 0.0f;
        #pragma unroll
        for (int i = 0; i < 8; i++) tot += red[i];
        atomicAdd(&g_S[c], tot);
    }
}

// ============================ kernel 2: stats C = A^T A (symmetric: 3 tiles) ============================
// grid (3, 64): bx 0->(0,0) 1->(1,1) 2->(0,1); by -> 2048-m chunk (32 slabs of 64 m).
#define ST_STRIDE 72
#define ST_BUF_B  36864                    // 256 rows * 144 B
#define ST_TOTAL  73728

__global__ void __launch_bounds__(256, 2) k_stats() {
    extern __shared__ char smem[];
    uint32_t sb_u = smem_u32(smem);

    int tid = threadIdx.x, warp = tid >> 5, lane = tid & 31;
    int ti = (blockIdx.x == 1) ? 1 : 0;
    int tj = (blockIdx.x == 0) ? 0 : 1;
    bool diag = (ti == tj);
    int rows = diag ? 128 : 256;
    int chunk = blockIdx.y;

    int mw = (warp >> 2) * 64;
    int nw = (warp & 3) * 32;
    int g = lane >> 2, t = lane & 3;

    float acc[16][4];
    #pragma unroll
    for (int i = 0; i < 16; i++)
        #pragma unroll
        for (int j = 0; j < 4; j++) acc[i][j] = 0.0f;

    uint32_t aoff = (uint32_t)((mw + (lane & 15)) * ST_STRIDE + (lane >> 4) * 8) * 2u;
    uint32_t boff_frag = (uint32_t)((nw + (lane & 7) + ((lane >> 4) << 3)) * ST_STRIDE
                                    + ((lane >> 3) & 1) * 8) * 2u;

    auto issue = [&](int sb, int buf) {
        int mtile = chunk * 16 + (sb >> 1);
        int m0 = (sb & 1) * 64;
        uint32_t dstb = sb_u + (uint32_t)buf * ST_BUF_B;
        const __half* srcb = g_a + (size_t)mtile * 32768 + m0;
        for (int u = tid; u < rows * 8; u += 256) {
            int r = u >> 3, part = u & 7;
            int krow = (r < 128) ? ti * 128 + r : tj * 128 + (r - 128);
            cp_async16(dstb + (uint32_t)(r * 144 + part * 16),
                       srcb + (size_t)krow * 128 + part * 8);
        }
        CP_COMMIT();
    };

    issue(0, 0);
    for (int sb = 0; sb < 32; sb++) {
        if (sb + 1 < 32) { issue(sb + 1, (sb + 1) & 1); CP_WAIT1(); }
        else             { CP_WAIT0(); }
        __syncthreads();

        uint32_t bufb = sb_u + (uint32_t)((sb & 1) * ST_BUF_B);
        uint32_t aaddr = bufb + aoff;
        uint32_t bbase = bufb + (diag ? 0u : (uint32_t)(128 * 144)) + boff_frag;
        #pragma unroll
        for (int ks = 0; ks < 4; ks++) {
            uint32_t afr[4][4];
            #pragma unroll
            for (int mi = 0; mi < 4; mi++)
                ldsm_x4(afr[mi][0], afr[mi][1], afr[mi][2], afr[mi][3],
                        aaddr + (uint32_t)(mi * 16 * ST_STRIDE + ks * 16) * 2u);
            uint32_t bfr[2][4];
            #pragma unroll
            for (int nip = 0; nip < 2; nip++)
                ldsm_x4(bfr[nip][0], bfr[nip][1], bfr[nip][2], bfr[nip][3],
                        bbase + (uint32_t)(nip * 16 * ST_STRIDE + ks * 16) * 2u);
            #pragma unroll
            for (int mi = 0; mi < 4; mi++)
                #pragma unroll
                for (int ni = 0; ni < 4; ni++)
                    mma16816(acc[mi * 4 + ni], afr[mi],
                             bfr[ni >> 1][(ni & 1) * 2], bfr[ni >> 1][(ni & 1) * 2 + 1]);
        }
        __syncthreads();
    }

    #pragma unroll
    for (int mi = 0; mi < 4; mi++)
        #pragma unroll
        for (int ni = 0; ni < 4; ni++) {
            int ci = ti * 128 + mw + mi * 16 + g;
            int cj = tj * 128 + nw + ni * 8 + t * 2;
            atomicAdd(&g_C[ci * CIN + cj],           acc[mi * 4 + ni][0]);
            atomicAdd(&g_C[ci * CIN + cj + 1],       acc[mi * 4 + ni][1]);
            atomicAdd(&g_C[(ci + 8) * CIN + cj],     acc[mi * 4 + ni][2]);
            atomicAdd(&g_C[(ci + 8) * CIN + cj + 1], acc[mi * 4 + ni][3]);
        }
}

// ============================ kernel 2b: mirror C upper -> lower ============================
__global__ void k_mirr() {
    int idx = blockIdx.x * 256 + threadIdx.x;     // 0..16383
    int r = idx >> 7, c2 = idx & 127;             // r in [0,128), c2 in [0,128)
    g_C[(128 + c2) * CIN + r] = g_C[r * CIN + 128 + c2];
}

// ============================ kernel 3: ssq partials (bilinear r-split) ============================
// grid (128, 4): bx = 4-channel group, by = 64-row r-quarter.
// ssq_part = sum_{r in quarter} sum_c w_r * C[r][c] * w_c  (bilinear -> additive over r).
__global__ void __launch_bounds__(256) k_fin(void) {
    __shared__ float smw[4][64];
    __shared__ float sred[8][4];
    int tid = threadIdx.x, warp = tid >> 5, lane = tid & 31;
    int o0 = blockIdx.x * 4;
    int r0 = blockIdx.y * 64;

    {   // smw[q][j] = w[o0+q][r0+j]
        int q = tid >> 6, j = tid & 63;
        smw[q][j] = __half2float(g_w[(size_t)(o0 + q) * KTOT + r0 + j]);
    }
    __syncthreads();

    float wv[4];
    #pragma unroll
    for (int q = 0; q < 4; q++) wv[q] = __half2float(g_w[(size_t)(o0 + q) * KTOT + tid]);

    float u[4] = {0.0f, 0.0f, 0.0f, 0.0f};
    #pragma unroll 8
    for (int j = 0; j < 64; j++) {
        float cr = g_C[(r0 + j) * CIN + tid];
        #pragma unroll
        for (int q = 0; q < 4; q++) u[q] += smw[q][j] * cr;
    }
    float p[4];
    #pragma unroll
    for (int q = 0; q < 4; q++) {
        p[q] = u[q] * wv[q];
        #pragma unroll
        for (int off = 16; off; off >>= 1) p[q] += __shfl_xor_sync(0xFFFFFFFFu, p[q], off);
    }
    if (lane == 0) {
        #pragma unroll
        for (int q = 0; q < 4; q++) sred[warp][q] = p[q];
    }
    __syncthreads();
    if (tid < 4) {
        float tot = 0.0f;
        #pragma unroll
        for (int w2 = 0; w2 < 8; w2++) tot += sred[w2][tid];
        atomicAdd(&g_ssq[o0 + tid], tot);
    }
}

// ============================ kernel 3b: finalize gabe ============================
__global__ void k_fin2(const float* __restrict__ gamma, const float* __restrict__ beta) {
    __shared__ float sS[256];
    int tid = threadIdx.x;
    if (tid < 256) sS[tid] = g_S[tid];
    __syncthreads();
    int o = blockIdx.x * 256 + tid;
    float mean = 0.0f;
    #pragma unroll 8
    for (int c = 0; c < 256; c++)
        mean += __half2float(g_w[(size_t)o * KTOT + c]) * sS[c];
    mean *= (1.0f / NPIX);
    float ey2 = g_ssq[o] * (1.0f / NPIX);
    float var = ey2 - mean * mean;
    float inv = rsqrtf(var + 1e-5f);
    float ga = gamma[o] * inv;
    float be = beta[o] - mean * ga;
    g_gabe[o] = make_float2(ga, be);
}

// ============================ kernel 4: GEMM + fused normalize -> out ============================
// A prefab fp16, full-K resident via cp.async burst. B per-phase plain loads.
// Epilogue: per-warp transpose buffers (8n x 68m fp32 each), __syncwarp only.
#define SMA_OFF    0                       // [256 k][136 m] half = 69632 B
#define SMB_OFF    69632                   // 18432 B (B tile / per-warp transpose buffers)
#define SM_TOTAL   88064
#define SMA_STRIDE 136
#define SMB_STRIDE 72

__global__ void __launch_bounds__(256, 2) k_gemm(float* __restrict__ out) {
    extern __shared__ char smem[];
    __half* smB = (__half*)(smem + SMB_OFF);
    uint32_t smA_u = smem_u32(smem);
    uint32_t smB_u = smem_u32(smB);

    int tid = threadIdx.x, warp = tid >> 5, lane = tid & 31;
    int mtile = blockIdx.x;            // 0..1023
    int b   = mtile >> 5;
    int hw0 = (mtile & 31) << 7;

    int mw = (warp >> 2) * 64;
    int nw = (warp & 3) * 32;
    int brow = tid & 127, bpart = tid >> 7;
    int g = lane >> 2, t = lane & 3;

    // prologue: cp.async full A tile (256 rows x 128 m fp16 = 256 B/row -> 16 parts)
    {
        const __half* srcb = g_a + (size_t)mtile * 32768;
        #pragma unroll
        for (int it = 0; it < 16; it++) {
            int u = it * 256 + tid;
            int r = u >> 4, part = u & 15;
            cp_async16(smA_u + (uint32_t)(r * 272 + part * 16),
                       srcb + (size_t)r * 128 + part * 8);
        }
        CP_COMMIT();
    }

    float acc[16][4];
    #pragma unroll
    for (int i = 0; i < 16; i++)
        #pragma unroll
        for (int j = 0; j < 4; j++) acc[i][j] = 0.0f;

    uint32_t aaddr = smA_u + (uint32_t)(((lane & 7) + ((lane >> 4) << 3)) * SMA_STRIDE
                                        + mw + ((lane >> 3) & 1) * 8) * 2u;
    uint32_t blane = smB_u + (uint32_t)((nw + (lane & 7) + ((lane >> 4) << 3)) * SMB_STRIDE
                                        + ((lane >> 3) & 1) * 8) * 2u;

    for (int nt = 0; nt < 4; nt++) {
        for (int kc = 0; kc < 4; kc++) {
            {   // B tile (nt, kc) from L2-resident weights
                const uint4* src = (const uint4*)(g_w + (size_t)(nt * 128 + brow) * KTOT
                                                  + kc * 64 + bpart * 32);
                uint4* dst = (uint4*)(smB + brow * SMB_STRIDE + bpart * 32);
                dst[0] = src[0]; dst[1] = src[1]; dst[2] = src[2]; dst[3] = src[3];
            }
            if (nt == 0 && kc == 0) CP_WAIT0();      // A tile resident
            __syncthreads();

            uint32_t abase = aaddr + (uint32_t)(kc * 64 * SMA_STRIDE) * 2u;
            #pragma unroll
            for (int ks = 0; ks < 4; ks++) {
                uint32_t afr[4][4];
                #pragma unroll
                for (int mi = 0; mi < 4; mi++)
                    ldsm_x4_t(afr[mi][0], afr[mi][1], afr[mi][2], afr[mi][3],
                              abase + (uint32_t)(ks * 16 * SMA_STRIDE + mi * 16) * 2u);
                uint32_t bfr[2][4];
                #pragma unroll
                for (int nip = 0; nip < 2; nip++)
                    ldsm_x4(bfr[nip][0], bfr[nip][1], bfr[nip][2], bfr[nip][3],
                            blane + (uint32_t)(nip * 16 * SMB_STRIDE + ks * 16) * 2u);
                #pragma unroll
                for (int mi = 0; mi < 4; mi++)
                    #pragma unroll
                    for (int ni = 0; ni < 4; ni++)
                        mma16816(acc[mi * 4 + ni], afr[mi],
                                 bfr[ni >> 1][(ni & 1) * 2], bfr[ni >> 1][(ni & 1) * 2 + 1]);
            }
            __syncthreads();
        }

        // ---- epilogue: per-warp transpose + normalize + coalesced fp32 stores ----
        float2 gb[8];
        #pragma unroll
        for (int ni = 0; ni < 4; ni++) {
            int n = nt * 128 + nw + ni * 8 + t * 2;
            gb[ni * 2]     = g_gabe[n];
            gb[ni * 2 + 1] = g_gabe[n + 1];
        }
        float* smW = (float*)(smem + SMB_OFF) + warp * 544;   // 8n x 68m floats
        #pragma unroll
        for (int ni = 0; ni < 4; ni++) {
            float2 q0 = gb[ni * 2], q1 = gb[ni * 2 + 1];
            #pragma unroll
            for (int mi = 0; mi < 4; mi++) {
                int mloc = mi * 16 + g;
                smW[(t * 2) * 68 + mloc]         = acc[mi * 4 + ni][0] * q0.x + q0.y;
                smW[(t * 2 + 1) * 68 + mloc]     = acc[mi * 4 + ni][1] * q1.x + q1.y;
                smW[(t * 2) * 68 + mloc + 8]     = acc[mi * 4 + ni][2] * q0.x + q0.y;
                smW[(t * 2 + 1) * 68 + mloc + 8] = acc[mi * 4 + ni][3] * q1.x + q1.y;
                acc[mi * 4 + ni][0] = 0.0f; acc[mi * 4 + ni][1] = 0.0f;
                acc[mi * 4 + ni][2] = 0.0f; acc[mi * 4 + ni][3] = 0.0f;
            }
            __syncwarp();
            // store 8 n-rows x 64 m (256 B per row, two rows per 32-lane transaction set)
            #pragma unroll
            for (int it = 0; it < 4; it++) {
                int u = it * 32 + lane;          // 0..127 float4 units
                int r = u >> 4, part = u & 15;
                float4 v = *(float4*)(smW + r * 68 + part * 4);
                __stcs((float4*)(out + ((size_t)(b * COUT + nt * 128 + nw + ni * 8 + r)) * HWSZ
                                 + hw0 + mw + part * 4), v);
            }
            __syncwarp();
        }
        __syncthreads();                 // all warps done with smB region before next B staging
    }
}

// ============================ launcher ============================
extern "C" void kernel_launch(void* const* d_in, const int* in_sizes, int n_in,
                              void* d_out, int out_size) {
    const float* x     = (const float*)d_in[0];
    const float* w     = (const float*)d_in[1];
    // d_in[2] = conv_b: exactly cancelled by BatchNorm mean subtraction.
    const float* gamma = (const float*)d_in[3];
    const float* beta  = (const float*)d_in[4];
    float* out = (float*)d_out;

    cudaFuncSetAttribute(k_stats, cudaFuncAttributeMaxDynamicSharedMemorySize, ST_TOTAL);
    cudaFuncSetAttribute(k_gemm,  cudaFuncAttributeMaxDynamicSharedMemorySize, SM_TOTAL);

    k_init<<<4096, 256>>>(w);                      // noise + fp16 W + zero C/S/ssq
    k_prep<<<32768, 256>>>(x);                     // A = relu(x+noise) fp16 tiles + S
    k_stats<<<dim3(3, 64), 256, ST_TOTAL>>>();     // C upper (symmetry: 3 of 4 tiles)
    k_mirr<<<64, 256>>>();                         // mirror C upper -> lower
    k_fin<<<dim3(128, 4), 256>>>();                // ssq partials (r-split bilinear)
    k_fin2<<<2, 256>>>(gamma, beta);               // mean + (ga, be)
    k_gemm<<<1024, 256, SM_TOTAL>>>(out);          // y -> normalize -> out (per-warp epi)
}